// round 13
// baseline (speedup 1.0000x reference)
#include <cuda_runtime.h>
#include <cuda_fp16.h>
#include <stdint.h>
#include <stddef.h>

// ---------------------------------------------------------------------------
// Problem constants
// ---------------------------------------------------------------------------
#define TOK   4096          // B*S tokens
#define DIN   4096
#define DOUT  4096
#define NE    8             // experts
#define RL    16            // lora rank
#define JD    128           // NE*RL
#define NSPLIT 8            // K-splits for k_low

// ---------------------------------------------------------------------------
// Scratch (static device globals: allocation-free rule)
// ---------------------------------------------------------------------------
static __device__ __half g_xh  [(size_t)TOK  * DIN];   // x fp16
static __device__ __half g_wh  [(size_t)DOUT * DIN];   // base_w fp16
static __device__ __half g_lah [(size_t)JD   * DIN];   // lora_A fp16
static __device__ __half g_bch [(size_t)DOUT * JD];    // Bcat fp16
static __device__ __half g_zh  [(size_t)TOK  * JD];    // z = gs*low fp16
static __device__ float  g_lowp[NSPLIT][(size_t)TOK * JD]; // split-K partials
static __device__ float  g_gs  [(size_t)TOK  * NE];    // routing weights * SCALING

// ---------------------------------------------------------------------------
// PTX helpers
// ---------------------------------------------------------------------------
__device__ __forceinline__ uint32_t smem_u32(const void* p) {
    uint32_t a;
    asm("{ .reg .u64 t; cvta.to.shared.u64 t, %1; cvt.u32.u64 %0, t; }"
        : "=r"(a) : "l"(p));
    return a;
}

__device__ __forceinline__ void ldsm_x4(uint32_t& r0, uint32_t& r1,
                                        uint32_t& r2, uint32_t& r3,
                                        uint32_t addr) {
    asm volatile("ldmatrix.sync.aligned.m8n8.x4.shared.b16 {%0,%1,%2,%3}, [%4];"
                 : "=r"(r0), "=r"(r1), "=r"(r2), "=r"(r3) : "r"(addr));
}

__device__ __forceinline__ void mma16816(float& c0, float& c1, float& c2, float& c3,
                                         uint32_t a0, uint32_t a1, uint32_t a2, uint32_t a3,
                                         uint32_t b0, uint32_t b1) {
    asm volatile(
        "mma.sync.aligned.m16n8k16.row.col.f32.f16.f16.f32 "
        "{%0,%1,%2,%3}, {%4,%5,%6,%7}, {%8,%9}, {%0,%1,%2,%3};"
        : "+f"(c0), "+f"(c1), "+f"(c2), "+f"(c3)
        : "r"(a0), "r"(a1), "r"(a2), "r"(a3), "r"(b0), "r"(b1));
}

#define CP_ASYNC16(smem, gptr)                                         \
    asm volatile("cp.async.cg.shared.global [%0], [%1], 16;"           \
                 :: "r"(smem), "l"(gptr))
#define CP_COMMIT() asm volatile("cp.async.commit_group;" ::: "memory")
#define CP_WAIT1()  asm volatile("cp.async.wait_group 1;" ::: "memory")
#define CP_WAIT0()  asm volatile("cp.async.wait_group 0;" ::: "memory")

__device__ __forceinline__ uint32_t sw128(uint32_t off) {
    return off ^ ((off >> 3) & 0x70);
}

// ---------------------------------------------------------------------------
// k_prepA: gate (+x->fp16) | lora_A->fp16 | lora_B pack  (feeds k_low chain)
//   blocks [0,256): gate, 16 tokens each (R10 config)
//   blocks [256,384): lora_A conv
//   blocks [384,448): Bcat pack
// ---------------------------------------------------------------------------
#define PA_GATE 256
#define PA_LA   128
#define PA_GRID (PA_GATE + PA_LA + 64)

__global__ void __launch_bounds__(256) k_prepA(const float* __restrict__ x,
                                               const float* __restrict__ gw,
                                               const float4* __restrict__ la,
                                               const float* __restrict__ lb) {
    __shared__ float4 sgw[NE * 128];      // 16 KB (gate blocks only)
    const int bid = blockIdx.x;
    const int tid = threadIdx.x;

    if (bid < PA_GATE) {
        // ---------------- gate + x conversion (2 tokens per warp) ----------
        const int wid = tid >> 5, lane = tid & 31;
        const int t0 = bid * 16 + wid * 2;

        float acc[2][NE];
#pragma unroll
        for (int tt = 0; tt < 2; tt++)
#pragma unroll
            for (int e = 0; e < NE; e++) acc[tt][e] = 0.f;

        for (int ch = 0; ch < DIN / 512; ch++) {
#pragma unroll
            for (int i = tid; i < NE * 128; i += 256) {
                int e = i >> 7, c = i & 127;
                sgw[i] = reinterpret_cast<const float4*>(
                    gw + (size_t)e * DIN + ch * 512)[c];
            }
            __syncthreads();
#pragma unroll
            for (int tt = 0; tt < 2; tt++) {
                const float4* xr = reinterpret_cast<const float4*>(
                    x + (size_t)(t0 + tt) * DIN + ch * 512);
                __half2* xo = reinterpret_cast<__half2*>(
                    g_xh + (size_t)(t0 + tt) * DIN + ch * 512);
#pragma unroll
                for (int j0 = 0; j0 < 4; j0++) {
                    int j = lane + j0 * 32;
                    float4 v = xr[j];
                    xo[2 * j]     = __floats2half2_rn(v.x, v.y);
                    xo[2 * j + 1] = __floats2half2_rn(v.z, v.w);
#pragma unroll
                    for (int e = 0; e < NE; e++) {
                        float4 w = sgw[e * 128 + j];
                        acc[tt][e] = fmaf(v.x, w.x,
                                     fmaf(v.y, w.y,
                                     fmaf(v.z, w.z,
                                     fmaf(v.w, w.w, acc[tt][e]))));
                    }
                }
            }
            __syncthreads();
        }

#pragma unroll
        for (int tt = 0; tt < 2; tt++)
#pragma unroll
            for (int e = 0; e < NE; e++)
                for (int o = 16; o; o >>= 1)
                    acc[tt][e] += __shfl_xor_sync(0xffffffffu, acc[tt][e], o);

        if (lane == 0) {
#pragma unroll
            for (int tt = 0; tt < 2; tt++) {
                float* lg = acc[tt];
                int i1 = 0;
                for (int e = 1; e < NE; e++) if (lg[e] > lg[i1]) i1 = e;
                int i2 = (i1 == 0) ? 1 : 0;
                for (int e = 0; e < NE; e++)
                    if (e != i1 && lg[e] > lg[i2]) i2 = e;
                float e2 = expf(lg[i2] - lg[i1]);
                float inv = 1.f / (1.f + e2);
                float* o = g_gs + (size_t)(t0 + tt) * NE;
#pragma unroll
                for (int e = 0; e < NE; e++) o[e] = 0.f;
                o[i1] = 2.0f * inv;        // SCALING = 2.0 folded
                o[i2] = 2.0f * e2 * inv;
            }
        }
    } else if (bid < PA_GATE + PA_LA) {
        // ---------------- lora_A -> fp16 ----------------
        const int n4 = (JD * DIN) / 4;   // 131072
        for (int i = (bid - PA_GATE) * 256 + tid; i < n4; i += PA_LA * 256) {
            float4 v = la[i];
            __half2* o = reinterpret_cast<__half2*>(g_lah + (size_t)i * 4);
            o[0] = __floats2half2_rn(v.x, v.y);
            o[1] = __floats2half2_rn(v.z, v.w);
        }
    } else {
        // ---------------- conv_bc: lora_B -> Bcat fp16 ----------------
        for (int idx = (bid - PA_GATE - PA_LA) * 256 + tid;
             idx < NE * DOUT * RL; idx += 64 * 256) {
            int e = idx >> 16;
            int rem = idx & 0xFFFF;
            int o = rem >> 4;
            int r = rem & 15;
            g_bch[(size_t)o * JD + e * RL + r] = __float2half(lb[idx]);
        }
    }
}

// ---------------------------------------------------------------------------
// k_prepB: base_w -> fp16 (independent; runs on second stream)
// ---------------------------------------------------------------------------
#define PB_BLKS 2048

__global__ void __launch_bounds__(256) k_prepB(const float4* __restrict__ bw) {
    const int n4 = (DOUT * DIN) / 4;       // 4194304
    const int stride = PB_BLKS * 256;
    for (int i0 = blockIdx.x * 256 + threadIdx.x; i0 < n4; i0 += 4 * stride) {
        float4 v[4];
        bool ok[4];
#pragma unroll
        for (int u = 0; u < 4; u++) {
            int i = i0 + u * stride;
            ok[u] = (i < n4);
            if (ok[u]) v[u] = bw[i];
        }
#pragma unroll
        for (int u = 0; u < 4; u++) {
            if (ok[u]) {
                int i = i0 + u * stride;
                __half2* o = reinterpret_cast<__half2*>(g_wh + (size_t)i * 4);
                o[0] = __floats2half2_rn(v[u].x, v[u].y);
                o[1] = __floats2half2_rn(v[u].z, v[u].w);
            }
        }
    }
}

// ---------------------------------------------------------------------------
// Shared GEMM tile machinery constants
// ---------------------------------------------------------------------------
#define BK 64
#define NSTAGE 3
#define T_STAGE (128 * BK * 2)   // 16 KB per operand per stage
#define B_OFF   (NSTAGE * T_STAGE)
#define SMEM_TOTAL (2 * NSTAGE * T_STAGE)   // 96 KB

// ---------------------------------------------------------------------------
// k_low: split-K GEMM  low_partial[s] = x[., s*512..] @ lora_A[., s*512..]^T
// ---------------------------------------------------------------------------
__global__ void __launch_bounds__(256, 2)
k_low() {
    extern __shared__ __align__(1024) char smem[];
    const uint32_t sbase = smem_u32(smem);

    const int tid = threadIdx.x;
    const int wid = tid >> 5, lane = tid & 31;
    const int warp_m = wid & 1;
    const int warp_n = wid >> 1;
    const int split = blockIdx.x;

    const int ld_row = tid >> 3;
    const int ld_chk = tid & 7;
    const __half* gA = g_xh + ((size_t)blockIdx.y * 128 + ld_row) * DIN +
                       split * (DIN / NSPLIT) + ld_chk * 8;
    const __half* gB = g_lah + (size_t)ld_row * DIN +
                       split * (DIN / NSPLIT) + ld_chk * 8;

    uint32_t stOff[4];
#pragma unroll
    for (int p = 0; p < 4; p++)
        stOff[p] = sw128((uint32_t)(ld_row + 32 * p) * 128 + ld_chk * 16);

    const int aRow = warp_m * 64 + (lane & 15);
    const int aColH = (lane >> 4) * 8;
    const int bRow = warp_n * 32 + (lane & 7) + ((lane >> 4) * 8);
    const int bColH = ((lane >> 3) & 1) * 8;

    float acc[4][4][4];
#pragma unroll
    for (int mi = 0; mi < 4; mi++)
#pragma unroll
        for (int ni = 0; ni < 4; ni++)
#pragma unroll
            for (int c = 0; c < 4; c++) acc[mi][ni][c] = 0.f;

    const int NK = (DIN / NSPLIT) / BK;   // 8

    auto issue = [&](int kstage) {
        const int st = kstage % NSTAGE;
        const __half* ga = gA + kstage * BK;
        const __half* gb = gB + kstage * BK;
        const uint32_t aBuf = sbase + st * T_STAGE;
        const uint32_t bBuf = sbase + B_OFF + st * T_STAGE;
#pragma unroll
        for (int p = 0; p < 4; p++) {
            CP_ASYNC16(aBuf + stOff[p], ga + (size_t)(32 * p) * DIN);
            CP_ASYNC16(bBuf + stOff[p], gb + (size_t)(32 * p) * DIN);
        }
    };

    issue(0); CP_COMMIT();
    issue(1); CP_COMMIT();

    for (int kc = 0; kc < NK; kc++) {
        CP_WAIT1();
        __syncthreads();
        if (kc + 2 < NK) issue(kc + 2);
        CP_COMMIT();

        const uint32_t aT = sbase + (kc % NSTAGE) * T_STAGE;
        const uint32_t bT = sbase + B_OFF + (kc % NSTAGE) * T_STAGE;

#pragma unroll
        for (int ks = 0; ks < BK / 16; ks++) {
            uint32_t af[4][4];
#pragma unroll
            for (int mi = 0; mi < 4; mi++) {
                uint32_t off = (uint32_t)(aRow + mi * 16) * 128 +
                               (uint32_t)(aColH + ks * 16) * 2;
                ldsm_x4(af[mi][0], af[mi][1], af[mi][2], af[mi][3],
                        aT + sw128(off));
            }
            uint32_t bf[2][4];
#pragma unroll
            for (int ni2 = 0; ni2 < 2; ni2++) {
                uint32_t off = (uint32_t)(bRow + ni2 * 16) * 128 +
                               (uint32_t)(bColH + ks * 16) * 2;
                ldsm_x4(bf[ni2][0], bf[ni2][1], bf[ni2][2], bf[ni2][3],
                        bT + sw128(off));
            }
#pragma unroll
            for (int mi = 0; mi < 4; mi++) {
#pragma unroll
                for (int ni = 0; ni < 4; ni++) {
                    uint32_t b0 = bf[ni >> 1][(ni & 1) * 2 + 0];
                    uint32_t b1 = bf[ni >> 1][(ni & 1) * 2 + 1];
                    mma16816(acc[mi][ni][0], acc[mi][ni][1],
                             acc[mi][ni][2], acc[mi][ni][3],
                             af[mi][0], af[mi][1], af[mi][2], af[mi][3],
                             b0, b1);
                }
            }
        }
    }

    float* outp = g_lowp[split];
    const int rowBase = blockIdx.y * 128 + warp_m * 64 + (lane >> 2);
    const int colBase = warp_n * 32 + (lane & 3) * 2;
#pragma unroll
    for (int mi = 0; mi < 4; mi++) {
#pragma unroll
        for (int ni = 0; ni < 4; ni++) {
            int r0 = rowBase + mi * 16;
            int c0 = colBase + ni * 8;
            float* o = outp + (size_t)r0 * JD + c0;
            o[0] = acc[mi][ni][0];
            o[1] = acc[mi][ni][1];
            o += 8 * JD;
            o[0] = acc[mi][ni][2];
            o[1] = acc[mi][ni][3];
        }
    }
}

// ---------------------------------------------------------------------------
// k_z: z = gs * sum_s lowp[s] -> fp16
// ---------------------------------------------------------------------------
__global__ void __launch_bounds__(256) k_z() {
    int i = blockIdx.x * blockDim.x + threadIdx.x;   // half2 index
    if (i < TOK * JD / 2) {
        int t = i >> 6;
        int j = (i & 63) * 2;
        float s0 = 0.f, s1 = 0.f;
#pragma unroll
        for (int s = 0; s < NSPLIT; s++) {
            const float* p = g_lowp[s] + (size_t)t * JD + j;
            s0 += p[0];
            s1 += p[1];
        }
        float g = g_gs[(size_t)t * NE + (j >> 4)];
        reinterpret_cast<__half2*>(g_zh)[i] = __floats2half2_rn(g * s0, g * s1);
    }
}

// ---------------------------------------------------------------------------
// k_gemm1: out = x @ base_w^T + bias + z @ Bcat^T (unchanged from R10)
// ---------------------------------------------------------------------------
__global__ void __launch_bounds__(256, 2)
k_gemm1(const float* __restrict__ bias, float* __restrict__ out) {
    extern __shared__ __align__(1024) char smem[];
    const uint32_t sbase = smem_u32(smem);

    const int tid = threadIdx.x;
    const int wid = tid >> 5, lane = tid & 31;
    const int warp_m = wid & 1;
    const int warp_n = wid >> 1;

    const int ld_row = tid >> 3;
    const int ld_chk = tid & 7;
    const __half* gA = g_xh + ((size_t)blockIdx.y * 128 + ld_row) * DIN + ld_chk * 8;
    const __half* gB = g_wh + ((size_t)blockIdx.x * 128 + ld_row) * DIN + ld_chk * 8;

    uint32_t stOff[4];
#pragma unroll
    for (int p = 0; p < 4; p++)
        stOff[p] = sw128((uint32_t)(ld_row + 32 * p) * 128 + ld_chk * 16);

    const int aRow = warp_m * 64 + (lane & 15);
    const int aColH = (lane >> 4) * 8;
    const int bRow = warp_n * 32 + (lane & 7) + ((lane >> 4) * 8);
    const int bColH = ((lane >> 3) & 1) * 8;

    float acc[4][4][4];
#pragma unroll
    for (int mi = 0; mi < 4; mi++)
#pragma unroll
        for (int ni = 0; ni < 4; ni++)
#pragma unroll
            for (int c = 0; c < 4; c++) acc[mi][ni][c] = 0.f;

    const int NK = DIN / BK;

    auto issue = [&](int kstage) {
        const int st = kstage % NSTAGE;
        const __half* ga = gA + kstage * BK;
        const __half* gb = gB + kstage * BK;
        const uint32_t aBuf = sbase + st * T_STAGE;
        const uint32_t bBuf = sbase + B_OFF + st * T_STAGE;
#pragma unroll
        for (int p = 0; p < 4; p++) {
            CP_ASYNC16(aBuf + stOff[p], ga + (size_t)(32 * p) * DIN);
            CP_ASYNC16(bBuf + stOff[p], gb + (size_t)(32 * p) * DIN);
        }
    };

    issue(0); CP_COMMIT();
    issue(1); CP_COMMIT();

    for (int kc = 0; kc < NK; kc++) {
        CP_WAIT1();
        __syncthreads();
        if (kc + 2 < NK) issue(kc + 2);
        CP_COMMIT();

        const uint32_t aT = sbase + (kc % NSTAGE) * T_STAGE;
        const uint32_t bT = sbase + B_OFF + (kc % NSTAGE) * T_STAGE;

#pragma unroll
        for (int ks = 0; ks < BK / 16; ks++) {
            uint32_t af[4][4];
#pragma unroll
            for (int mi = 0; mi < 4; mi++) {
                uint32_t off = (uint32_t)(aRow + mi * 16) * 128 +
                               (uint32_t)(aColH + ks * 16) * 2;
                ldsm_x4(af[mi][0], af[mi][1], af[mi][2], af[mi][3],
                        aT + sw128(off));
            }
            uint32_t bf[2][4];
#pragma unroll
            for (int ni2 = 0; ni2 < 2; ni2++) {
                uint32_t off = (uint32_t)(bRow + ni2 * 16) * 128 +
                               (uint32_t)(bColH + ks * 16) * 2;
                ldsm_x4(bf[ni2][0], bf[ni2][1], bf[ni2][2], bf[ni2][3],
                        bT + sw128(off));
            }
#pragma unroll
            for (int mi = 0; mi < 4; mi++) {
#pragma unroll
                for (int ni = 0; ni < 4; ni++) {
                    uint32_t b0 = bf[ni >> 1][(ni & 1) * 2 + 0];
                    uint32_t b1 = bf[ni >> 1][(ni & 1) * 2 + 1];
                    mma16816(acc[mi][ni][0], acc[mi][ni][1],
                             acc[mi][ni][2], acc[mi][ni][3],
                             af[mi][0], af[mi][1], af[mi][2], af[mi][3],
                             b0, b1);
                }
            }
        }
    }

    // ---------------- LoRA tail: acc += z @ Bcat^T (K = JD = 128) ----------
    __syncthreads();   // all warps done reading stage buffers
    {
        const __half* gZ = g_zh + ((size_t)blockIdx.y * 128 + ld_row) * JD + ld_chk * 8;
        const __half* gC = g_bch + ((size_t)blockIdx.x * 128 + ld_row) * JD + ld_chk * 8;
#pragma unroll
        for (int kc = 0; kc < 2; kc++) {
#pragma unroll
            for (int p = 0; p < 4; p++) {
                CP_ASYNC16(sbase + kc * T_STAGE + stOff[p],
                           gZ + kc * 64 + (size_t)(32 * p) * JD);
                CP_ASYNC16(sbase + B_OFF + kc * T_STAGE + stOff[p],
                           gC + kc * 64 + (size_t)(32 * p) * JD);
            }
        }
        CP_COMMIT();
        CP_WAIT0();
        __syncthreads();

#pragma unroll
        for (int kc = 0; kc < 2; kc++) {
            const uint32_t aT = sbase + kc * T_STAGE;
            const uint32_t bT = sbase + B_OFF + kc * T_STAGE;
#pragma unroll
            for (int ks = 0; ks < 4; ks++) {
                uint32_t af[4][4];
#pragma unroll
                for (int mi = 0; mi < 4; mi++) {
                    uint32_t off = (uint32_t)(aRow + mi * 16) * 128 +
                                   (uint32_t)(aColH + ks * 16) * 2;
                    ldsm_x4(af[mi][0], af[mi][1], af[mi][2], af[mi][3],
                            aT + sw128(off));
                }
                uint32_t bf[2][4];
#pragma unroll
                for (int ni2 = 0; ni2 < 2; ni2++) {
                    uint32_t off = (uint32_t)(bRow + ni2 * 16) * 128 +
                                   (uint32_t)(bColH + ks * 16) * 2;
                    ldsm_x4(bf[ni2][0], bf[ni2][1], bf[ni2][2], bf[ni2][3],
                            bT + sw128(off));
                }
#pragma unroll
                for (int mi = 0; mi < 4; mi++) {
#pragma unroll
                    for (int ni = 0; ni < 4; ni++) {
                        uint32_t b0 = bf[ni >> 1][(ni & 1) * 2 + 0];
                        uint32_t b1 = bf[ni >> 1][(ni & 1) * 2 + 1];
                        mma16816(acc[mi][ni][0], acc[mi][ni][1],
                                 acc[mi][ni][2], acc[mi][ni][3],
                                 af[mi][0], af[mi][1], af[mi][2], af[mi][3],
                                 b0, b1);
                    }
                }
            }
        }
    }

    // ---------------- epilogue: out = acc + bias (no RMW) ----------------
    const int rowBase = blockIdx.y * 128 + warp_m * 64 + (lane >> 2);
    const int colBase = blockIdx.x * 128 + warp_n * 32 + (lane & 3) * 2;
#pragma unroll
    for (int mi = 0; mi < 4; mi++) {
#pragma unroll
        for (int ni = 0; ni < 4; ni++) {
            int r0 = rowBase + mi * 16;
            int c0 = colBase + ni * 8;
            float* o = out + (size_t)r0 * DOUT + c0;
            float b0 = __ldg(bias + c0);
            float b1 = __ldg(bias + c0 + 1);
            o[0] = acc[mi][ni][0] + b0;
            o[1] = acc[mi][ni][1] + b1;
            o += 8 * DOUT;
            o[0] = acc[mi][ni][2] + b0;
            o[1] = acc[mi][ni][3] + b1;
        }
    }
}

// ---------------------------------------------------------------------------
// Launcher: fork base_w conversion onto a second stream, join before gemm1.
//   Streams/events created once on first (uncaptured) call; event record/wait
//   is graph-capturable and forms the fork-join edges.
// ---------------------------------------------------------------------------
extern "C" void kernel_launch(void* const* d_in, const int* in_sizes, int n_in,
                              void* d_out, int out_size) {
    const float* x      = (const float*)d_in[0];
    const float* gate_w = (const float*)d_in[1];
    const float* base_w = (const float*)d_in[2];
    const float* base_b = (const float*)d_in[3];
    const float* lora_A = (const float*)d_in[4];
    const float* lora_B = (const float*)d_in[5];
    float* out = (float*)d_out;

    static cudaStream_t s2 = nullptr;
    static cudaEvent_t ev_fork = nullptr, ev_join = nullptr;
    if (s2 == nullptr) {
        cudaStreamCreateWithFlags(&s2, cudaStreamNonBlocking);
        cudaEventCreateWithFlags(&ev_fork, cudaEventDisableTiming);
        cudaEventCreateWithFlags(&ev_join, cudaEventDisableTiming);
        cudaFuncSetAttribute(k_low,
                             cudaFuncAttributeMaxDynamicSharedMemorySize, SMEM_TOTAL);
        cudaFuncSetAttribute(k_gemm1,
                             cudaFuncAttributeMaxDynamicSharedMemorySize, SMEM_TOTAL);
    }

    // fork: base_w conversion on s2
    cudaEventRecord(ev_fork, 0);
    cudaStreamWaitEvent(s2, ev_fork, 0);
    k_prepB<<<PB_BLKS, 256, 0, s2>>>((const float4*)base_w);
    cudaEventRecord(ev_join, s2);

    // main chain: gate/x/lora_A/Bcat -> low -> z
    k_prepA<<<PA_GRID, 256>>>(x, gate_w, (const float4*)lora_A, lora_B);
    k_low<<<dim3(NSPLIT, TOK / 128), 256, SMEM_TOTAL>>>();
    k_z<<<(TOK * JD / 2 + 255) / 256, 256>>>();

    // join, then fused big GEMM
    cudaStreamWaitEvent(0, ev_join, 0);
    k_gemm1<<<dim3(DOUT / 128, TOK / 128), 256, SMEM_TOTAL>>>(base_b, out);
}

// round 14
// speedup vs baseline: 1.0254x; 1.0254x over previous
#include <cuda_runtime.h>
#include <cuda_fp16.h>
#include <stdint.h>
#include <stddef.h>

// ---------------------------------------------------------------------------
// Problem constants
// ---------------------------------------------------------------------------
#define TOK   4096          // B*S tokens
#define DIN   4096
#define DOUT  4096
#define NE    8             // experts
#define RL    16            // lora rank
#define JD    128           // NE*RL
#define NSPLIT 8            // K-splits for k_low

// ---------------------------------------------------------------------------
// Scratch (static device globals: allocation-free rule)
// ---------------------------------------------------------------------------
static __device__ __half g_xh  [(size_t)TOK  * DIN];   // x fp16
static __device__ __half g_wh  [(size_t)DOUT * DIN];   // base_w fp16
static __device__ __half g_lah [(size_t)JD   * DIN];   // lora_A fp16
static __device__ __half g_bch [(size_t)DOUT * JD];    // Bcat fp16
static __device__ __half g_zh  [(size_t)TOK  * JD];    // z = gs*low fp16
static __device__ float  g_lowp[NSPLIT][(size_t)TOK * JD]; // split-K partials
static __device__ float  g_gs  [(size_t)TOK  * NE];    // routing weights * SCALING

// ---------------------------------------------------------------------------
// PTX helpers
// ---------------------------------------------------------------------------
__device__ __forceinline__ uint32_t smem_u32(const void* p) {
    uint32_t a;
    asm("{ .reg .u64 t; cvta.to.shared.u64 t, %1; cvt.u32.u64 %0, t; }"
        : "=r"(a) : "l"(p));
    return a;
}

__device__ __forceinline__ void ldsm_x4(uint32_t& r0, uint32_t& r1,
                                        uint32_t& r2, uint32_t& r3,
                                        uint32_t addr) {
    asm volatile("ldmatrix.sync.aligned.m8n8.x4.shared.b16 {%0,%1,%2,%3}, [%4];"
                 : "=r"(r0), "=r"(r1), "=r"(r2), "=r"(r3) : "r"(addr));
}

__device__ __forceinline__ void mma16816(float& c0, float& c1, float& c2, float& c3,
                                         uint32_t a0, uint32_t a1, uint32_t a2, uint32_t a3,
                                         uint32_t b0, uint32_t b1) {
    asm volatile(
        "mma.sync.aligned.m16n8k16.row.col.f32.f16.f16.f32 "
        "{%0,%1,%2,%3}, {%4,%5,%6,%7}, {%8,%9}, {%0,%1,%2,%3};"
        : "+f"(c0), "+f"(c1), "+f"(c2), "+f"(c3)
        : "r"(a0), "r"(a1), "r"(a2), "r"(a3), "r"(b0), "r"(b1));
}

#define CP_ASYNC16(smem, gptr)                                         \
    asm volatile("cp.async.cg.shared.global [%0], [%1], 16;"           \
                 :: "r"(smem), "l"(gptr))
#define CP_COMMIT() asm volatile("cp.async.commit_group;" ::: "memory")
#define CP_WAIT1()  asm volatile("cp.async.wait_group 1;" ::: "memory")
#define CP_WAIT0()  asm volatile("cp.async.wait_group 0;" ::: "memory")

__device__ __forceinline__ uint32_t sw128(uint32_t off) {
    return off ^ ((off >> 3) & 0x70);
}

// ---------------------------------------------------------------------------
// k_prep: gate (+x->fp16) | base_w/lora_A->fp16 | lora_B pack  (R10 shape)
// ---------------------------------------------------------------------------
#define PREP_GATE_BLKS 256
#define PREP_CONVW_BLKS 2048
#define PREP_GRID (PREP_GATE_BLKS + PREP_CONVW_BLKS + 64)

__global__ void __launch_bounds__(256) k_prep(const float* __restrict__ x,
                                              const float* __restrict__ gw,
                                              const float4* __restrict__ bw,
                                              const float4* __restrict__ la,
                                              const float* __restrict__ lb) {
    __shared__ float4 sgw[NE * 128];      // 16 KB (gate blocks only)
    const int bid = blockIdx.x;
    const int tid = threadIdx.x;

    if (bid < PREP_GATE_BLKS) {
        // ---------------- gate + x conversion ----------------
        const int wid = tid >> 5, lane = tid & 31;
        const int t0 = bid * 16 + wid * 2;

        float acc[2][NE];
#pragma unroll
        for (int tt = 0; tt < 2; tt++)
#pragma unroll
            for (int e = 0; e < NE; e++) acc[tt][e] = 0.f;

        for (int ch = 0; ch < DIN / 512; ch++) {
#pragma unroll
            for (int i = tid; i < NE * 128; i += 256) {
                int e = i >> 7, c = i & 127;
                sgw[i] = reinterpret_cast<const float4*>(
                    gw + (size_t)e * DIN + ch * 512)[c];
            }
            __syncthreads();
#pragma unroll
            for (int tt = 0; tt < 2; tt++) {
                const float4* xr = reinterpret_cast<const float4*>(
                    x + (size_t)(t0 + tt) * DIN + ch * 512);
                __half2* xo = reinterpret_cast<__half2*>(
                    g_xh + (size_t)(t0 + tt) * DIN + ch * 512);
#pragma unroll
                for (int j0 = 0; j0 < 4; j0++) {
                    int j = lane + j0 * 32;
                    float4 v = xr[j];
                    xo[2 * j]     = __floats2half2_rn(v.x, v.y);
                    xo[2 * j + 1] = __floats2half2_rn(v.z, v.w);
#pragma unroll
                    for (int e = 0; e < NE; e++) {
                        float4 w = sgw[e * 128 + j];
                        acc[tt][e] = fmaf(v.x, w.x,
                                     fmaf(v.y, w.y,
                                     fmaf(v.z, w.z,
                                     fmaf(v.w, w.w, acc[tt][e]))));
                    }
                }
            }
            __syncthreads();
        }

#pragma unroll
        for (int tt = 0; tt < 2; tt++)
#pragma unroll
            for (int e = 0; e < NE; e++)
                for (int o = 16; o; o >>= 1)
                    acc[tt][e] += __shfl_xor_sync(0xffffffffu, acc[tt][e], o);

        if (lane == 0) {
#pragma unroll
            for (int tt = 0; tt < 2; tt++) {
                float* lg = acc[tt];
                int i1 = 0;
                for (int e = 1; e < NE; e++) if (lg[e] > lg[i1]) i1 = e;
                int i2 = (i1 == 0) ? 1 : 0;
                for (int e = 0; e < NE; e++)
                    if (e != i1 && lg[e] > lg[i2]) i2 = e;
                float e2 = expf(lg[i2] - lg[i1]);
                float inv = 1.f / (1.f + e2);
                float* o = g_gs + (size_t)(t0 + tt) * NE;
#pragma unroll
                for (int e = 0; e < NE; e++) o[e] = 0.f;
                o[i1] = 2.0f * inv;        // SCALING = 2.0 folded
                o[i2] = 2.0f * e2 * inv;
            }
        }
    } else if (bid < PREP_GATE_BLKS + PREP_CONVW_BLKS) {
        // ------- conv: base_w -> g_wh ; lora_A -> g_lah (4-way MLP) -------
        const int n4_base = (DOUT * DIN) / 4;
        const int n4_tot  = n4_base + (JD * DIN) / 4;
        const int stride  = PREP_CONVW_BLKS * 256;
        for (int i0 = (bid - PREP_GATE_BLKS) * 256 + tid; i0 < n4_tot;
             i0 += 4 * stride) {
            float4 v[4];
            bool ok[4];
#pragma unroll
            for (int u = 0; u < 4; u++) {
                int i = i0 + u * stride;
                ok[u] = (i < n4_tot);
                if (ok[u]) v[u] = (i < n4_base) ? bw[i] : la[i - n4_base];
            }
#pragma unroll
            for (int u = 0; u < 4; u++) {
                if (ok[u]) {
                    int i = i0 + u * stride;
                    __half2* o = (i < n4_base)
                        ? reinterpret_cast<__half2*>(g_wh + (size_t)i * 4)
                        : reinterpret_cast<__half2*>(g_lah + (size_t)(i - n4_base) * 4);
                    o[0] = __floats2half2_rn(v[u].x, v[u].y);
                    o[1] = __floats2half2_rn(v[u].z, v[u].w);
                }
            }
        }
    } else {
        // ---------------- conv_bc: lora_B -> Bcat fp16 ----------------
        for (int idx = (bid - PREP_GATE_BLKS - PREP_CONVW_BLKS) * 256 + tid;
             idx < NE * DOUT * RL; idx += 64 * 256) {
            int e = idx >> 16;
            int rem = idx & 0xFFFF;
            int o = rem >> 4;
            int r = rem & 15;
            g_bch[(size_t)o * JD + e * RL + r] = __float2half(lb[idx]);
        }
    }
}

// ---------------------------------------------------------------------------
// Shared GEMM tile machinery constants
// ---------------------------------------------------------------------------
#define BK 64
#define NSTAGE 3
#define T_STAGE (128 * BK * 2)   // 16 KB per operand per stage
#define B_OFF   (NSTAGE * T_STAGE)
#define SMEM_TOTAL (2 * NSTAGE * T_STAGE)   // 96 KB

// ---------------------------------------------------------------------------
// k_low: split-K GEMM  low_partial[s] = x[., s*512..] @ lora_A[., s*512..]^T
// ---------------------------------------------------------------------------
__global__ void __launch_bounds__(256, 2)
k_low() {
    extern __shared__ __align__(1024) char smem[];
    const uint32_t sbase = smem_u32(smem);

    const int tid = threadIdx.x;
    const int wid = tid >> 5, lane = tid & 31;
    const int warp_m = wid & 1;
    const int warp_n = wid >> 1;
    const int split = blockIdx.x;

    const int ld_row = tid >> 3;
    const int ld_chk = tid & 7;
    const __half* gA = g_xh + ((size_t)blockIdx.y * 128 + ld_row) * DIN +
                       split * (DIN / NSPLIT) + ld_chk * 8;
    const __half* gB = g_lah + (size_t)ld_row * DIN +
                       split * (DIN / NSPLIT) + ld_chk * 8;

    uint32_t stOff[4];
#pragma unroll
    for (int p = 0; p < 4; p++)
        stOff[p] = sw128((uint32_t)(ld_row + 32 * p) * 128 + ld_chk * 16);

    const int aRow = warp_m * 64 + (lane & 15);
    const int aColH = (lane >> 4) * 8;
    const int bRow = warp_n * 32 + (lane & 7) + ((lane >> 4) * 8);
    const int bColH = ((lane >> 3) & 1) * 8;

    float acc[4][4][4];
#pragma unroll
    for (int mi = 0; mi < 4; mi++)
#pragma unroll
        for (int ni = 0; ni < 4; ni++)
#pragma unroll
            for (int c = 0; c < 4; c++) acc[mi][ni][c] = 0.f;

    const int NK = (DIN / NSPLIT) / BK;   // 8

    auto issue = [&](int kstage) {
        const int st = kstage % NSTAGE;
        const __half* ga = gA + kstage * BK;
        const __half* gb = gB + kstage * BK;
        const uint32_t aBuf = sbase + st * T_STAGE;
        const uint32_t bBuf = sbase + B_OFF + st * T_STAGE;
#pragma unroll
        for (int p = 0; p < 4; p++) {
            CP_ASYNC16(aBuf + stOff[p], ga + (size_t)(32 * p) * DIN);
            CP_ASYNC16(bBuf + stOff[p], gb + (size_t)(32 * p) * DIN);
        }
    };

    issue(0); CP_COMMIT();
    issue(1); CP_COMMIT();

    for (int kc = 0; kc < NK; kc++) {
        CP_WAIT1();
        __syncthreads();
        if (kc + 2 < NK) issue(kc + 2);
        CP_COMMIT();

        const uint32_t aT = sbase + (kc % NSTAGE) * T_STAGE;
        const uint32_t bT = sbase + B_OFF + (kc % NSTAGE) * T_STAGE;

#pragma unroll
        for (int ks = 0; ks < BK / 16; ks++) {
            uint32_t af[4][4];
#pragma unroll
            for (int mi = 0; mi < 4; mi++) {
                uint32_t off = (uint32_t)(aRow + mi * 16) * 128 +
                               (uint32_t)(aColH + ks * 16) * 2;
                ldsm_x4(af[mi][0], af[mi][1], af[mi][2], af[mi][3],
                        aT + sw128(off));
            }
            uint32_t bf[2][4];
#pragma unroll
            for (int ni2 = 0; ni2 < 2; ni2++) {
                uint32_t off = (uint32_t)(bRow + ni2 * 16) * 128 +
                               (uint32_t)(bColH + ks * 16) * 2;
                ldsm_x4(bf[ni2][0], bf[ni2][1], bf[ni2][2], bf[ni2][3],
                        bT + sw128(off));
            }
#pragma unroll
            for (int mi = 0; mi < 4; mi++) {
#pragma unroll
                for (int ni = 0; ni < 4; ni++) {
                    uint32_t b0 = bf[ni >> 1][(ni & 1) * 2 + 0];
                    uint32_t b1 = bf[ni >> 1][(ni & 1) * 2 + 1];
                    mma16816(acc[mi][ni][0], acc[mi][ni][1],
                             acc[mi][ni][2], acc[mi][ni][3],
                             af[mi][0], af[mi][1], af[mi][2], af[mi][3],
                             b0, b1);
                }
            }
        }
    }

    float* outp = g_lowp[split];
    const int rowBase = blockIdx.y * 128 + warp_m * 64 + (lane >> 2);
    const int colBase = warp_n * 32 + (lane & 3) * 2;
#pragma unroll
    for (int mi = 0; mi < 4; mi++) {
#pragma unroll
        for (int ni = 0; ni < 4; ni++) {
            int r0 = rowBase + mi * 16;
            int c0 = colBase + ni * 8;
            float* o = outp + (size_t)r0 * JD + c0;
            o[0] = acc[mi][ni][0];
            o[1] = acc[mi][ni][1];
            o += 8 * JD;
            o[0] = acc[mi][ni][2];
            o[1] = acc[mi][ni][3];
        }
    }
}

// ---------------------------------------------------------------------------
// k_z: z = gs * sum_s lowp[s] -> fp16   (float4-vectorized: 4 outputs/thread)
// ---------------------------------------------------------------------------
__global__ void __launch_bounds__(256) k_z() {
    int i = blockIdx.x * blockDim.x + threadIdx.x;   // float4 index
    if (i < TOK * JD / 4) {
        int t = i >> 5;            // 32 float4 per token
        int j = (i & 31) * 4;      // 4 consecutive j, same expert (16-aligned grp)
        float4 s = make_float4(0.f, 0.f, 0.f, 0.f);
#pragma unroll
        for (int sp = 0; sp < NSPLIT; sp++) {
            float4 p = reinterpret_cast<const float4*>(g_lowp[sp])[i];
            s.x += p.x; s.y += p.y; s.z += p.z; s.w += p.w;
        }
        float g = g_gs[(size_t)t * NE + (j >> 4)];
        __half2* o = reinterpret_cast<__half2*>(g_zh) + 2 * i;
        o[0] = __floats2half2_rn(g * s.x, g * s.y);
        o[1] = __floats2half2_rn(g * s.z, g * s.w);
    }
}

// ---------------------------------------------------------------------------
// k_gemm1: out = x @ base_w^T + bias + z @ Bcat^T  (R10 version)
// ---------------------------------------------------------------------------
__global__ void __launch_bounds__(256, 2)
k_gemm1(const float* __restrict__ bias, float* __restrict__ out) {
    extern __shared__ __align__(1024) char smem[];
    const uint32_t sbase = smem_u32(smem);

    const int tid = threadIdx.x;
    const int wid = tid >> 5, lane = tid & 31;
    const int warp_m = wid & 1;
    const int warp_n = wid >> 1;

    const int ld_row = tid >> 3;
    const int ld_chk = tid & 7;
    const __half* gA = g_xh + ((size_t)blockIdx.y * 128 + ld_row) * DIN + ld_chk * 8;
    const __half* gB = g_wh + ((size_t)blockIdx.x * 128 + ld_row) * DIN + ld_chk * 8;

    uint32_t stOff[4];
#pragma unroll
    for (int p = 0; p < 4; p++)
        stOff[p] = sw128((uint32_t)(ld_row + 32 * p) * 128 + ld_chk * 16);

    const int aRow = warp_m * 64 + (lane & 15);
    const int aColH = (lane >> 4) * 8;
    const int bRow = warp_n * 32 + (lane & 7) + ((lane >> 4) * 8);
    const int bColH = ((lane >> 3) & 1) * 8;

    float acc[4][4][4];
#pragma unroll
    for (int mi = 0; mi < 4; mi++)
#pragma unroll
        for (int ni = 0; ni < 4; ni++)
#pragma unroll
            for (int c = 0; c < 4; c++) acc[mi][ni][c] = 0.f;

    const int NK = DIN / BK;

    auto issue = [&](int kstage) {
        const int st = kstage % NSTAGE;
        const __half* ga = gA + kstage * BK;
        const __half* gb = gB + kstage * BK;
        const uint32_t aBuf = sbase + st * T_STAGE;
        const uint32_t bBuf = sbase + B_OFF + st * T_STAGE;
#pragma unroll
        for (int p = 0; p < 4; p++) {
            CP_ASYNC16(aBuf + stOff[p], ga + (size_t)(32 * p) * DIN);
            CP_ASYNC16(bBuf + stOff[p], gb + (size_t)(32 * p) * DIN);
        }
    };

    issue(0); CP_COMMIT();
    issue(1); CP_COMMIT();

    for (int kc = 0; kc < NK; kc++) {
        CP_WAIT1();
        __syncthreads();
        if (kc + 2 < NK) issue(kc + 2);
        CP_COMMIT();

        const uint32_t aT = sbase + (kc % NSTAGE) * T_STAGE;
        const uint32_t bT = sbase + B_OFF + (kc % NSTAGE) * T_STAGE;

#pragma unroll
        for (int ks = 0; ks < BK / 16; ks++) {
            uint32_t af[4][4];
#pragma unroll
            for (int mi = 0; mi < 4; mi++) {
                uint32_t off = (uint32_t)(aRow + mi * 16) * 128 +
                               (uint32_t)(aColH + ks * 16) * 2;
                ldsm_x4(af[mi][0], af[mi][1], af[mi][2], af[mi][3],
                        aT + sw128(off));
            }
            uint32_t bf[2][4];
#pragma unroll
            for (int ni2 = 0; ni2 < 2; ni2++) {
                uint32_t off = (uint32_t)(bRow + ni2 * 16) * 128 +
                               (uint32_t)(bColH + ks * 16) * 2;
                ldsm_x4(bf[ni2][0], bf[ni2][1], bf[ni2][2], bf[ni2][3],
                        bT + sw128(off));
            }
#pragma unroll
            for (int mi = 0; mi < 4; mi++) {
#pragma unroll
                for (int ni = 0; ni < 4; ni++) {
                    uint32_t b0 = bf[ni >> 1][(ni & 1) * 2 + 0];
                    uint32_t b1 = bf[ni >> 1][(ni & 1) * 2 + 1];
                    mma16816(acc[mi][ni][0], acc[mi][ni][1],
                             acc[mi][ni][2], acc[mi][ni][3],
                             af[mi][0], af[mi][1], af[mi][2], af[mi][3],
                             b0, b1);
                }
            }
        }
    }

    // ---------------- LoRA tail: acc += z @ Bcat^T (K = JD = 128) ----------
    __syncthreads();   // all warps done reading stage buffers
    {
        const __half* gZ = g_zh + ((size_t)blockIdx.y * 128 + ld_row) * JD + ld_chk * 8;
        const __half* gC = g_bch + ((size_t)blockIdx.x * 128 + ld_row) * JD + ld_chk * 8;
#pragma unroll
        for (int kc = 0; kc < 2; kc++) {
#pragma unroll
            for (int p = 0; p < 4; p++) {
                CP_ASYNC16(sbase + kc * T_STAGE + stOff[p],
                           gZ + kc * 64 + (size_t)(32 * p) * JD);
                CP_ASYNC16(sbase + B_OFF + kc * T_STAGE + stOff[p],
                           gC + kc * 64 + (size_t)(32 * p) * JD);
            }
        }
        CP_COMMIT();
        CP_WAIT0();
        __syncthreads();

#pragma unroll
        for (int kc = 0; kc < 2; kc++) {
            const uint32_t aT = sbase + kc * T_STAGE;
            const uint32_t bT = sbase + B_OFF + kc * T_STAGE;
#pragma unroll
            for (int ks = 0; ks < 4; ks++) {
                uint32_t af[4][4];
#pragma unroll
                for (int mi = 0; mi < 4; mi++) {
                    uint32_t off = (uint32_t)(aRow + mi * 16) * 128 +
                                   (uint32_t)(aColH + ks * 16) * 2;
                    ldsm_x4(af[mi][0], af[mi][1], af[mi][2], af[mi][3],
                            aT + sw128(off));
                }
                uint32_t bf[2][4];
#pragma unroll
                for (int ni2 = 0; ni2 < 2; ni2++) {
                    uint32_t off = (uint32_t)(bRow + ni2 * 16) * 128 +
                                   (uint32_t)(bColH + ks * 16) * 2;
                    ldsm_x4(bf[ni2][0], bf[ni2][1], bf[ni2][2], bf[ni2][3],
                            bT + sw128(off));
                }
#pragma unroll
                for (int mi = 0; mi < 4; mi++) {
#pragma unroll
                    for (int ni = 0; ni < 4; ni++) {
                        uint32_t b0 = bf[ni >> 1][(ni & 1) * 2 + 0];
                        uint32_t b1 = bf[ni >> 1][(ni & 1) * 2 + 1];
                        mma16816(acc[mi][ni][0], acc[mi][ni][1],
                                 acc[mi][ni][2], acc[mi][ni][3],
                                 af[mi][0], af[mi][1], af[mi][2], af[mi][3],
                                 b0, b1);
                    }
                }
            }
        }
    }

    // ---------------- epilogue: out = acc + bias (no RMW) ----------------
    const int rowBase = blockIdx.y * 128 + warp_m * 64 + (lane >> 2);
    const int colBase = blockIdx.x * 128 + warp_n * 32 + (lane & 3) * 2;
#pragma unroll
    for (int mi = 0; mi < 4; mi++) {
#pragma unroll
        for (int ni = 0; ni < 4; ni++) {
            int r0 = rowBase + mi * 16;
            int c0 = colBase + ni * 8;
            float* o = out + (size_t)r0 * DOUT + c0;
            float b0 = __ldg(bias + c0);
            float b1 = __ldg(bias + c0 + 1);
            o[0] = acc[mi][ni][0] + b0;
            o[1] = acc[mi][ni][1] + b1;
            o += 8 * DOUT;
            o[0] = acc[mi][ni][2] + b0;
            o[1] = acc[mi][ni][3] + b1;
        }
    }
}

// ---------------------------------------------------------------------------
// Launcher (single stream, R10 ordering)
// ---------------------------------------------------------------------------
extern "C" void kernel_launch(void* const* d_in, const int* in_sizes, int n_in,
                              void* d_out, int out_size) {
    const float* x      = (const float*)d_in[0];
    const float* gate_w = (const float*)d_in[1];
    const float* base_w = (const float*)d_in[2];
    const float* base_b = (const float*)d_in[3];
    const float* lora_A = (const float*)d_in[4];
    const float* lora_B = (const float*)d_in[5];
    float* out = (float*)d_out;

    cudaFuncSetAttribute(k_low,
                         cudaFuncAttributeMaxDynamicSharedMemorySize, SMEM_TOTAL);
    cudaFuncSetAttribute(k_gemm1,
                         cudaFuncAttributeMaxDynamicSharedMemorySize, SMEM_TOTAL);

    // 1. prep: gate (+x conversion) | base_w/lora_A conversion | Bcat pack
    k_prep<<<PREP_GRID, 256>>>(x, gate_w, (const float4*)base_w,
                               (const float4*)lora_A, lora_B);

    // 2. low-rank activations, split-K partials
    k_low<<<dim3(NSPLIT, TOK / 128), 256, SMEM_TOTAL>>>();

    // 3. reduce partials, apply routing weights, emit fp16 z
    k_z<<<(TOK * JD / 4 + 255) / 256, 256>>>();

    // 4. fused: out = x@W^T + bias + z@Bcat^T
    k_gemm1<<<dim3(DOUT / 128, TOK / 128), 256, SMEM_TOTAL>>>(base_b, out);
}

// round 15
// speedup vs baseline: 1.0325x; 1.0070x over previous
#include <cuda_runtime.h>
#include <cuda_fp16.h>
#include <stdint.h>
#include <stddef.h>

// ---------------------------------------------------------------------------
// Problem constants
// ---------------------------------------------------------------------------
#define TOK   4096          // B*S tokens
#define DIN   4096
#define DOUT  4096
#define NE    8             // experts
#define RL    16            // lora rank
#define JD    128           // NE*RL
#define NSPLIT 8            // K-splits for k_low

// ---------------------------------------------------------------------------
// Scratch (static device globals: allocation-free rule)
// ---------------------------------------------------------------------------
static __device__ __half g_xh  [(size_t)TOK  * DIN];   // x fp16
static __device__ __half g_wh  [(size_t)DOUT * DIN];   // base_w fp16
static __device__ __half g_lah [(size_t)JD   * DIN];   // lora_A fp16
static __device__ __half g_bch [(size_t)DOUT * JD];    // Bcat fp16
static __device__ __half g_zh  [(size_t)TOK  * JD];    // z = gs*low fp16
static __device__ float  g_lowp[NSPLIT][(size_t)TOK * JD]; // split-K partials
static __device__ float  g_gs  [(size_t)TOK  * NE];    // routing weights * SCALING

// ---------------------------------------------------------------------------
// PTX helpers
// ---------------------------------------------------------------------------
__device__ __forceinline__ uint32_t smem_u32(const void* p) {
    uint32_t a;
    asm("{ .reg .u64 t; cvta.to.shared.u64 t, %1; cvt.u32.u64 %0, t; }"
        : "=r"(a) : "l"(p));
    return a;
}

__device__ __forceinline__ void ldsm_x4(uint32_t& r0, uint32_t& r1,
                                        uint32_t& r2, uint32_t& r3,
                                        uint32_t addr) {
    asm volatile("ldmatrix.sync.aligned.m8n8.x4.shared.b16 {%0,%1,%2,%3}, [%4];"
                 : "=r"(r0), "=r"(r1), "=r"(r2), "=r"(r3) : "r"(addr));
}

__device__ __forceinline__ void mma16816(float& c0, float& c1, float& c2, float& c3,
                                         uint32_t a0, uint32_t a1, uint32_t a2, uint32_t a3,
                                         uint32_t b0, uint32_t b1) {
    asm volatile(
        "mma.sync.aligned.m16n8k16.row.col.f32.f16.f16.f32 "
        "{%0,%1,%2,%3}, {%4,%5,%6,%7}, {%8,%9}, {%0,%1,%2,%3};"
        : "+f"(c0), "+f"(c1), "+f"(c2), "+f"(c3)
        : "r"(a0), "r"(a1), "r"(a2), "r"(a3), "r"(b0), "r"(b1));
}

#define CP_ASYNC16(smem, gptr)                                         \
    asm volatile("cp.async.cg.shared.global [%0], [%1], 16;"           \
                 :: "r"(smem), "l"(gptr))
#define CP_COMMIT() asm volatile("cp.async.commit_group;" ::: "memory")
#define CP_WAIT1()  asm volatile("cp.async.wait_group 1;" ::: "memory")
#define CP_WAIT0()  asm volatile("cp.async.wait_group 0;" ::: "memory")

__device__ __forceinline__ uint32_t sw128(uint32_t off) {
    return off ^ ((off >> 3) & 0x70);
}

// ---------------------------------------------------------------------------
// k_prep: gate (+x->fp16) | base_w/lora_A->fp16 | lora_B pack  (R10 shape)
// ---------------------------------------------------------------------------
#define PREP_GATE_BLKS 256
#define PREP_CONVW_BLKS 2048
#define PREP_GRID (PREP_GATE_BLKS + PREP_CONVW_BLKS + 64)

__global__ void __launch_bounds__(256) k_prep(const float* __restrict__ x,
                                              const float* __restrict__ gw,
                                              const float4* __restrict__ bw,
                                              const float4* __restrict__ la,
                                              const float* __restrict__ lb) {
    __shared__ float4 sgw[NE * 128];      // 16 KB (gate blocks only)
    const int bid = blockIdx.x;
    const int tid = threadIdx.x;

    if (bid < PREP_GATE_BLKS) {
        // ---------------- gate + x conversion ----------------
        const int wid = tid >> 5, lane = tid & 31;
        const int t0 = bid * 16 + wid * 2;

        float acc[2][NE];
#pragma unroll
        for (int tt = 0; tt < 2; tt++)
#pragma unroll
            for (int e = 0; e < NE; e++) acc[tt][e] = 0.f;

        for (int ch = 0; ch < DIN / 512; ch++) {
#pragma unroll
            for (int i = tid; i < NE * 128; i += 256) {
                int e = i >> 7, c = i & 127;
                sgw[i] = reinterpret_cast<const float4*>(
                    gw + (size_t)e * DIN + ch * 512)[c];
            }
            __syncthreads();
#pragma unroll
            for (int tt = 0; tt < 2; tt++) {
                const float4* xr = reinterpret_cast<const float4*>(
                    x + (size_t)(t0 + tt) * DIN + ch * 512);
                __half2* xo = reinterpret_cast<__half2*>(
                    g_xh + (size_t)(t0 + tt) * DIN + ch * 512);
#pragma unroll
                for (int j0 = 0; j0 < 4; j0++) {
                    int j = lane + j0 * 32;
                    float4 v = xr[j];
                    xo[2 * j]     = __floats2half2_rn(v.x, v.y);
                    xo[2 * j + 1] = __floats2half2_rn(v.z, v.w);
#pragma unroll
                    for (int e = 0; e < NE; e++) {
                        float4 w = sgw[e * 128 + j];
                        acc[tt][e] = fmaf(v.x, w.x,
                                     fmaf(v.y, w.y,
                                     fmaf(v.z, w.z,
                                     fmaf(v.w, w.w, acc[tt][e]))));
                    }
                }
            }
            __syncthreads();
        }

#pragma unroll
        for (int tt = 0; tt < 2; tt++)
#pragma unroll
            for (int e = 0; e < NE; e++)
                for (int o = 16; o; o >>= 1)
                    acc[tt][e] += __shfl_xor_sync(0xffffffffu, acc[tt][e], o);

        if (lane == 0) {
#pragma unroll
            for (int tt = 0; tt < 2; tt++) {
                float* lg = acc[tt];
                int i1 = 0;
                for (int e = 1; e < NE; e++) if (lg[e] > lg[i1]) i1 = e;
                int i2 = (i1 == 0) ? 1 : 0;
                for (int e = 0; e < NE; e++)
                    if (e != i1 && lg[e] > lg[i2]) i2 = e;
                float e2 = expf(lg[i2] - lg[i1]);
                float inv = 1.f / (1.f + e2);
                float* o = g_gs + (size_t)(t0 + tt) * NE;
#pragma unroll
                for (int e = 0; e < NE; e++) o[e] = 0.f;
                o[i1] = 2.0f * inv;        // SCALING = 2.0 folded
                o[i2] = 2.0f * e2 * inv;
            }
        }
    } else if (bid < PREP_GATE_BLKS + PREP_CONVW_BLKS) {
        // ------- conv: base_w -> g_wh ; lora_A -> g_lah (4-way MLP) -------
        const int n4_base = (DOUT * DIN) / 4;
        const int n4_tot  = n4_base + (JD * DIN) / 4;
        const int stride  = PREP_CONVW_BLKS * 256;
        for (int i0 = (bid - PREP_GATE_BLKS) * 256 + tid; i0 < n4_tot;
             i0 += 4 * stride) {
            float4 v[4];
            bool ok[4];
#pragma unroll
            for (int u = 0; u < 4; u++) {
                int i = i0 + u * stride;
                ok[u] = (i < n4_tot);
                if (ok[u]) v[u] = (i < n4_base) ? bw[i] : la[i - n4_base];
            }
#pragma unroll
            for (int u = 0; u < 4; u++) {
                if (ok[u]) {
                    int i = i0 + u * stride;
                    __half2* o = (i < n4_base)
                        ? reinterpret_cast<__half2*>(g_wh + (size_t)i * 4)
                        : reinterpret_cast<__half2*>(g_lah + (size_t)(i - n4_base) * 4);
                    o[0] = __floats2half2_rn(v[u].x, v[u].y);
                    o[1] = __floats2half2_rn(v[u].z, v[u].w);
                }
            }
        }
    } else {
        // ---------------- conv_bc: lora_B -> Bcat fp16 ----------------
        for (int idx = (bid - PREP_GATE_BLKS - PREP_CONVW_BLKS) * 256 + tid;
             idx < NE * DOUT * RL; idx += 64 * 256) {
            int e = idx >> 16;
            int rem = idx & 0xFFFF;
            int o = rem >> 4;
            int r = rem & 15;
            g_bch[(size_t)o * JD + e * RL + r] = __float2half(lb[idx]);
        }
    }
}

// ---------------------------------------------------------------------------
// Shared GEMM tile machinery constants
// ---------------------------------------------------------------------------
#define BK 64
#define NSTAGE 3
#define T_STAGE (128 * BK * 2)   // 16 KB per operand per stage
#define B_OFF   (NSTAGE * T_STAGE)
#define X_OFF   (2 * NSTAGE * T_STAGE)       // extra buffer for Bcat chunk 0
#define SMEM_LOW  (2 * NSTAGE * T_STAGE)     // 96 KB (k_low, no extra)
#define SMEM_G1   (2 * NSTAGE * T_STAGE + T_STAGE)   // 112 KB (gemm1)

// ---------------------------------------------------------------------------
// k_low: split-K GEMM  low_partial[s] = x[., s*512..] @ lora_A[., s*512..]^T
// ---------------------------------------------------------------------------
__global__ void __launch_bounds__(256, 2)
k_low() {
    extern __shared__ __align__(1024) char smem[];
    const uint32_t sbase = smem_u32(smem);

    const int tid = threadIdx.x;
    const int wid = tid >> 5, lane = tid & 31;
    const int warp_m = wid & 1;
    const int warp_n = wid >> 1;
    const int split = blockIdx.x;

    const int ld_row = tid >> 3;
    const int ld_chk = tid & 7;
    const __half* gA = g_xh + ((size_t)blockIdx.y * 128 + ld_row) * DIN +
                       split * (DIN / NSPLIT) + ld_chk * 8;
    const __half* gB = g_lah + (size_t)ld_row * DIN +
                       split * (DIN / NSPLIT) + ld_chk * 8;

    uint32_t stOff[4];
#pragma unroll
    for (int p = 0; p < 4; p++)
        stOff[p] = sw128((uint32_t)(ld_row + 32 * p) * 128 + ld_chk * 16);

    const int aRow = warp_m * 64 + (lane & 15);
    const int aColH = (lane >> 4) * 8;
    const int bRow = warp_n * 32 + (lane & 7) + ((lane >> 4) * 8);
    const int bColH = ((lane >> 3) & 1) * 8;

    float acc[4][4][4];
#pragma unroll
    for (int mi = 0; mi < 4; mi++)
#pragma unroll
        for (int ni = 0; ni < 4; ni++)
#pragma unroll
            for (int c = 0; c < 4; c++) acc[mi][ni][c] = 0.f;

    const int NK = (DIN / NSPLIT) / BK;   // 8

    auto issue = [&](int kstage) {
        const int st = kstage % NSTAGE;
        const __half* ga = gA + kstage * BK;
        const __half* gb = gB + kstage * BK;
        const uint32_t aBuf = sbase + st * T_STAGE;
        const uint32_t bBuf = sbase + B_OFF + st * T_STAGE;
#pragma unroll
        for (int p = 0; p < 4; p++) {
            CP_ASYNC16(aBuf + stOff[p], ga + (size_t)(32 * p) * DIN);
            CP_ASYNC16(bBuf + stOff[p], gb + (size_t)(32 * p) * DIN);
        }
    };

    issue(0); CP_COMMIT();
    issue(1); CP_COMMIT();

    for (int kc = 0; kc < NK; kc++) {
        CP_WAIT1();
        __syncthreads();
        if (kc + 2 < NK) issue(kc + 2);
        CP_COMMIT();

        const uint32_t aT = sbase + (kc % NSTAGE) * T_STAGE;
        const uint32_t bT = sbase + B_OFF + (kc % NSTAGE) * T_STAGE;

#pragma unroll
        for (int ks = 0; ks < BK / 16; ks++) {
            uint32_t af[4][4];
#pragma unroll
            for (int mi = 0; mi < 4; mi++) {
                uint32_t off = (uint32_t)(aRow + mi * 16) * 128 +
                               (uint32_t)(aColH + ks * 16) * 2;
                ldsm_x4(af[mi][0], af[mi][1], af[mi][2], af[mi][3],
                        aT + sw128(off));
            }
            uint32_t bf[2][4];
#pragma unroll
            for (int ni2 = 0; ni2 < 2; ni2++) {
                uint32_t off = (uint32_t)(bRow + ni2 * 16) * 128 +
                               (uint32_t)(bColH + ks * 16) * 2;
                ldsm_x4(bf[ni2][0], bf[ni2][1], bf[ni2][2], bf[ni2][3],
                        bT + sw128(off));
            }
#pragma unroll
            for (int mi = 0; mi < 4; mi++) {
#pragma unroll
                for (int ni = 0; ni < 4; ni++) {
                    uint32_t b0 = bf[ni >> 1][(ni & 1) * 2 + 0];
                    uint32_t b1 = bf[ni >> 1][(ni & 1) * 2 + 1];
                    mma16816(acc[mi][ni][0], acc[mi][ni][1],
                             acc[mi][ni][2], acc[mi][ni][3],
                             af[mi][0], af[mi][1], af[mi][2], af[mi][3],
                             b0, b1);
                }
            }
        }
    }

    float* outp = g_lowp[split];
    const int rowBase = blockIdx.y * 128 + warp_m * 64 + (lane >> 2);
    const int colBase = warp_n * 32 + (lane & 3) * 2;
#pragma unroll
    for (int mi = 0; mi < 4; mi++) {
#pragma unroll
        for (int ni = 0; ni < 4; ni++) {
            int r0 = rowBase + mi * 16;
            int c0 = colBase + ni * 8;
            float* o = outp + (size_t)r0 * JD + c0;
            o[0] = acc[mi][ni][0];
            o[1] = acc[mi][ni][1];
            o += 8 * JD;
            o[0] = acc[mi][ni][2];
            o[1] = acc[mi][ni][3];
        }
    }
}

// ---------------------------------------------------------------------------
// k_z: z = gs * sum_s lowp[s] -> fp16   (float4-vectorized)
// ---------------------------------------------------------------------------
__global__ void __launch_bounds__(256) k_z() {
    int i = blockIdx.x * blockDim.x + threadIdx.x;   // float4 index
    if (i < TOK * JD / 4) {
        int t = i >> 5;
        int j = (i & 31) * 4;
        float4 s = make_float4(0.f, 0.f, 0.f, 0.f);
#pragma unroll
        for (int sp = 0; sp < NSPLIT; sp++) {
            float4 p = reinterpret_cast<const float4*>(g_lowp[sp])[i];
            s.x += p.x; s.y += p.y; s.z += p.z; s.w += p.w;
        }
        float g = g_gs[(size_t)t * NE + (j >> 4)];
        __half2* o = reinterpret_cast<__half2*>(g_zh) + 2 * i;
        o[0] = __floats2half2_rn(g * s.x, g * s.y);
        o[1] = __floats2half2_rn(g * s.z, g * s.w);
    }
}

// ---------------------------------------------------------------------------
// k_gemm1: out = x @ base_w^T + bias + z @ Bcat^T
//   R10 mainloop; NEW: Bcat K-chunk 0 prefetched into an extra 16 KB smem
//   buffer during the prologue (same commit group as stage 0), so the LoRA
//   tail loads only z (2 chunks) + Bcat chunk 1 (48 KB instead of 64 KB)
//   and starts its mmas one chunk earlier.
// ---------------------------------------------------------------------------
__global__ void __launch_bounds__(256, 2)
k_gemm1(const float* __restrict__ bias, float* __restrict__ out) {
    extern __shared__ __align__(1024) char smem[];
    const uint32_t sbase = smem_u32(smem);

    const int tid = threadIdx.x;
    const int wid = tid >> 5, lane = tid & 31;
    const int warp_m = wid & 1;
    const int warp_n = wid >> 1;

    const int ld_row = tid >> 3;
    const int ld_chk = tid & 7;
    const __half* gA = g_xh + ((size_t)blockIdx.y * 128 + ld_row) * DIN + ld_chk * 8;
    const __half* gB = g_wh + ((size_t)blockIdx.x * 128 + ld_row) * DIN + ld_chk * 8;
    const __half* gC = g_bch + ((size_t)blockIdx.x * 128 + ld_row) * JD + ld_chk * 8;

    uint32_t stOff[4];
#pragma unroll
    for (int p = 0; p < 4; p++)
        stOff[p] = sw128((uint32_t)(ld_row + 32 * p) * 128 + ld_chk * 16);

    const int aRow = warp_m * 64 + (lane & 15);
    const int aColH = (lane >> 4) * 8;
    const int bRow = warp_n * 32 + (lane & 7) + ((lane >> 4) * 8);
    const int bColH = ((lane >> 3) & 1) * 8;

    float acc[4][4][4];
#pragma unroll
    for (int mi = 0; mi < 4; mi++)
#pragma unroll
        for (int ni = 0; ni < 4; ni++)
#pragma unroll
            for (int c = 0; c < 4; c++) acc[mi][ni][c] = 0.f;

    const int NK = DIN / BK;

    auto issue = [&](int kstage) {
        const int st = kstage % NSTAGE;
        const __half* ga = gA + kstage * BK;
        const __half* gb = gB + kstage * BK;
        const uint32_t aBuf = sbase + st * T_STAGE;
        const uint32_t bBuf = sbase + B_OFF + st * T_STAGE;
#pragma unroll
        for (int p = 0; p < 4; p++) {
            CP_ASYNC16(aBuf + stOff[p], ga + (size_t)(32 * p) * DIN);
            CP_ASYNC16(bBuf + stOff[p], gb + (size_t)(32 * p) * DIN);
        }
    };

    // prologue: stage 0 + Bcat chunk 0 (into extra buffer) in one group
    issue(0);
#pragma unroll
    for (int p = 0; p < 4; p++)
        CP_ASYNC16(sbase + X_OFF + stOff[p], gC + (size_t)(32 * p) * JD);
    CP_COMMIT();
    issue(1); CP_COMMIT();

    for (int kc = 0; kc < NK; kc++) {
        CP_WAIT1();
        __syncthreads();
        if (kc + 2 < NK) issue(kc + 2);
        CP_COMMIT();

        const uint32_t aT = sbase + (kc % NSTAGE) * T_STAGE;
        const uint32_t bT = sbase + B_OFF + (kc % NSTAGE) * T_STAGE;

#pragma unroll
        for (int ks = 0; ks < BK / 16; ks++) {
            uint32_t af[4][4];
#pragma unroll
            for (int mi = 0; mi < 4; mi++) {
                uint32_t off = (uint32_t)(aRow + mi * 16) * 128 +
                               (uint32_t)(aColH + ks * 16) * 2;
                ldsm_x4(af[mi][0], af[mi][1], af[mi][2], af[mi][3],
                        aT + sw128(off));
            }
            uint32_t bf[2][4];
#pragma unroll
            for (int ni2 = 0; ni2 < 2; ni2++) {
                uint32_t off = (uint32_t)(bRow + ni2 * 16) * 128 +
                               (uint32_t)(bColH + ks * 16) * 2;
                ldsm_x4(bf[ni2][0], bf[ni2][1], bf[ni2][2], bf[ni2][3],
                        bT + sw128(off));
            }
#pragma unroll
            for (int mi = 0; mi < 4; mi++) {
#pragma unroll
                for (int ni = 0; ni < 4; ni++) {
                    uint32_t b0 = bf[ni >> 1][(ni & 1) * 2 + 0];
                    uint32_t b1 = bf[ni >> 1][(ni & 1) * 2 + 1];
                    mma16816(acc[mi][ni][0], acc[mi][ni][1],
                             acc[mi][ni][2], acc[mi][ni][3],
                             af[mi][0], af[mi][1], af[mi][2], af[mi][3],
                             b0, b1);
                }
            }
        }
    }

    // ---------------- LoRA tail: acc += z @ Bcat^T (K = JD = 128) ----------
    // Bcat chunk 0 already resident in the extra buffer (prologue prefetch).
    __syncthreads();   // all warps done reading stage buffers
    {
        const __half* gZ = g_zh + ((size_t)blockIdx.y * 128 + ld_row) * JD + ld_chk * 8;
#pragma unroll
        for (int kc = 0; kc < 2; kc++) {
#pragma unroll
            for (int p = 0; p < 4; p++)
                CP_ASYNC16(sbase + kc * T_STAGE + stOff[p],
                           gZ + kc * 64 + (size_t)(32 * p) * JD);
        }
#pragma unroll
        for (int p = 0; p < 4; p++)
            CP_ASYNC16(sbase + B_OFF + stOff[p],
                       gC + 64 + (size_t)(32 * p) * JD);
        CP_COMMIT();
        CP_WAIT0();
        __syncthreads();

#pragma unroll
        for (int kc = 0; kc < 2; kc++) {
            const uint32_t aT = sbase + kc * T_STAGE;
            const uint32_t bT = (kc == 0) ? (sbase + X_OFF) : (sbase + B_OFF);
#pragma unroll
            for (int ks = 0; ks < 4; ks++) {
                uint32_t af[4][4];
#pragma unroll
                for (int mi = 0; mi < 4; mi++) {
                    uint32_t off = (uint32_t)(aRow + mi * 16) * 128 +
                                   (uint32_t)(aColH + ks * 16) * 2;
                    ldsm_x4(af[mi][0], af[mi][1], af[mi][2], af[mi][3],
                            aT + sw128(off));
                }
                uint32_t bf[2][4];
#pragma unroll
                for (int ni2 = 0; ni2 < 2; ni2++) {
                    uint32_t off = (uint32_t)(bRow + ni2 * 16) * 128 +
                                   (uint32_t)(bColH + ks * 16) * 2;
                    ldsm_x4(bf[ni2][0], bf[ni2][1], bf[ni2][2], bf[ni2][3],
                            bT + sw128(off));
                }
#pragma unroll
                for (int mi = 0; mi < 4; mi++) {
#pragma unroll
                    for (int ni = 0; ni < 4; ni++) {
                        uint32_t b0 = bf[ni >> 1][(ni & 1) * 2 + 0];
                        uint32_t b1 = bf[ni >> 1][(ni & 1) * 2 + 1];
                        mma16816(acc[mi][ni][0], acc[mi][ni][1],
                                 acc[mi][ni][2], acc[mi][ni][3],
                                 af[mi][0], af[mi][1], af[mi][2], af[mi][3],
                                 b0, b1);
                    }
                }
            }
        }
    }

    // ---------------- epilogue: out = acc + bias (no RMW) ----------------
    const int rowBase = blockIdx.y * 128 + warp_m * 64 + (lane >> 2);
    const int colBase = blockIdx.x * 128 + warp_n * 32 + (lane & 3) * 2;
#pragma unroll
    for (int mi = 0; mi < 4; mi++) {
#pragma unroll
        for (int ni = 0; ni < 4; ni++) {
            int r0 = rowBase + mi * 16;
            int c0 = colBase + ni * 8;
            float* o = out + (size_t)r0 * DOUT + c0;
            float b0 = __ldg(bias + c0);
            float b1 = __ldg(bias + c0 + 1);
            o[0] = acc[mi][ni][0] + b0;
            o[1] = acc[mi][ni][1] + b1;
            o += 8 * DOUT;
            o[0] = acc[mi][ni][2] + b0;
            o[1] = acc[mi][ni][3] + b1;
        }
    }
}

// ---------------------------------------------------------------------------
// Launcher (single stream, best-known ordering)
// ---------------------------------------------------------------------------
extern "C" void kernel_launch(void* const* d_in, const int* in_sizes, int n_in,
                              void* d_out, int out_size) {
    const float* x      = (const float*)d_in[0];
    const float* gate_w = (const float*)d_in[1];
    const float* base_w = (const float*)d_in[2];
    const float* base_b = (const float*)d_in[3];
    const float* lora_A = (const float*)d_in[4];
    const float* lora_B = (const float*)d_in[5];
    float* out = (float*)d_out;

    cudaFuncSetAttribute(k_low,
                         cudaFuncAttributeMaxDynamicSharedMemorySize, SMEM_LOW);
    cudaFuncSetAttribute(k_gemm1,
                         cudaFuncAttributeMaxDynamicSharedMemorySize, SMEM_G1);

    // 1. prep: gate (+x conversion) | base_w/lora_A conversion | Bcat pack
    k_prep<<<PREP_GRID, 256>>>(x, gate_w, (const float4*)base_w,
                               (const float4*)lora_A, lora_B);

    // 2. low-rank activations, split-K partials
    k_low<<<dim3(NSPLIT, TOK / 128), 256, SMEM_LOW>>>();

    // 3. reduce partials, apply routing weights, emit fp16 z
    k_z<<<(TOK * JD / 4 + 255) / 256, 256>>>();

    // 4. fused: out = x@W^T + bias + z@Bcat^T
    k_gemm1<<<dim3(DOUT / 128, TOK / 128), 256, SMEM_G1>>>(base_b, out);
}

// round 16
// speedup vs baseline: 1.0601x; 1.0266x over previous
#include <cuda_runtime.h>
#include <cuda_fp16.h>
#include <stdint.h>
#include <stddef.h>

// ---------------------------------------------------------------------------
// Problem constants
// ---------------------------------------------------------------------------
#define TOK   4096          // B*S tokens
#define DIN   4096
#define DOUT  4096
#define NE    8             // experts
#define RL    16            // lora rank
#define JD    128           // NE*RL
#define NSPLIT 8            // K-splits for k_low

// ---------------------------------------------------------------------------
// Scratch (static device globals: allocation-free rule)
// ---------------------------------------------------------------------------
static __device__ __half g_xh  [(size_t)TOK  * DIN];   // x fp16
static __device__ __half g_wh  [(size_t)DOUT * DIN];   // base_w fp16
static __device__ __half g_lah [(size_t)JD   * DIN];   // lora_A fp16
static __device__ __half g_bch [(size_t)DOUT * JD];    // Bcat fp16
static __device__ __half g_zh  [(size_t)TOK  * JD];    // z = gs*low fp16
static __device__ float  g_lowp[NSPLIT][(size_t)TOK * JD]; // split-K partials
static __device__ float  g_gs  [(size_t)TOK  * NE];    // routing weights * SCALING

// ---------------------------------------------------------------------------
// PTX helpers
// ---------------------------------------------------------------------------
__device__ __forceinline__ uint32_t smem_u32(const void* p) {
    uint32_t a;
    asm("{ .reg .u64 t; cvta.to.shared.u64 t, %1; cvt.u32.u64 %0, t; }"
        : "=r"(a) : "l"(p));
    return a;
}

__device__ __forceinline__ void ldsm_x4(uint32_t& r0, uint32_t& r1,
                                        uint32_t& r2, uint32_t& r3,
                                        uint32_t addr) {
    asm volatile("ldmatrix.sync.aligned.m8n8.x4.shared.b16 {%0,%1,%2,%3}, [%4];"
                 : "=r"(r0), "=r"(r1), "=r"(r2), "=r"(r3) : "r"(addr));
}

__device__ __forceinline__ void mma16816(float& c0, float& c1, float& c2, float& c3,
                                         uint32_t a0, uint32_t a1, uint32_t a2, uint32_t a3,
                                         uint32_t b0, uint32_t b1) {
    asm volatile(
        "mma.sync.aligned.m16n8k16.row.col.f32.f16.f16.f32 "
        "{%0,%1,%2,%3}, {%4,%5,%6,%7}, {%8,%9}, {%0,%1,%2,%3};"
        : "+f"(c0), "+f"(c1), "+f"(c2), "+f"(c3)
        : "r"(a0), "r"(a1), "r"(a2), "r"(a3), "r"(b0), "r"(b1));
}

#define CP_ASYNC16(smem, gptr)                                         \
    asm volatile("cp.async.cg.shared.global [%0], [%1], 16;"           \
                 :: "r"(smem), "l"(gptr))
#define CP_COMMIT() asm volatile("cp.async.commit_group;" ::: "memory")
#define CP_WAIT1()  asm volatile("cp.async.wait_group 1;" ::: "memory")
#define CP_WAIT0()  asm volatile("cp.async.wait_group 0;" ::: "memory")

__device__ __forceinline__ uint32_t sw128(uint32_t off) {
    return off ^ ((off >> 3) & 0x70);
}

// ---------------------------------------------------------------------------
// k_prep: gate (+x->fp16) | base_w/lora_A->fp16 | lora_B pack  (R10 shape)
// ---------------------------------------------------------------------------
#define PREP_GATE_BLKS 256
#define PREP_CONVW_BLKS 2048
#define PREP_GRID (PREP_GATE_BLKS + PREP_CONVW_BLKS + 64)

__global__ void __launch_bounds__(256) k_prep(const float* __restrict__ x,
                                              const float* __restrict__ gw,
                                              const float4* __restrict__ bw,
                                              const float4* __restrict__ la,
                                              const float* __restrict__ lb) {
    __shared__ float4 sgw[NE * 128];      // 16 KB (gate blocks only)
    const int bid = blockIdx.x;
    const int tid = threadIdx.x;

    if (bid < PREP_GATE_BLKS) {
        // ---------------- gate + x conversion ----------------
        const int wid = tid >> 5, lane = tid & 31;
        const int t0 = bid * 16 + wid * 2;

        float acc[2][NE];
#pragma unroll
        for (int tt = 0; tt < 2; tt++)
#pragma unroll
            for (int e = 0; e < NE; e++) acc[tt][e] = 0.f;

        for (int ch = 0; ch < DIN / 512; ch++) {
#pragma unroll
            for (int i = tid; i < NE * 128; i += 256) {
                int e = i >> 7, c = i & 127;
                sgw[i] = reinterpret_cast<const float4*>(
                    gw + (size_t)e * DIN + ch * 512)[c];
            }
            __syncthreads();
#pragma unroll
            for (int tt = 0; tt < 2; tt++) {
                const float4* xr = reinterpret_cast<const float4*>(
                    x + (size_t)(t0 + tt) * DIN + ch * 512);
                __half2* xo = reinterpret_cast<__half2*>(
                    g_xh + (size_t)(t0 + tt) * DIN + ch * 512);
#pragma unroll
                for (int j0 = 0; j0 < 4; j0++) {
                    int j = lane + j0 * 32;
                    float4 v = xr[j];
                    xo[2 * j]     = __floats2half2_rn(v.x, v.y);
                    xo[2 * j + 1] = __floats2half2_rn(v.z, v.w);
#pragma unroll
                    for (int e = 0; e < NE; e++) {
                        float4 w = sgw[e * 128 + j];
                        acc[tt][e] = fmaf(v.x, w.x,
                                     fmaf(v.y, w.y,
                                     fmaf(v.z, w.z,
                                     fmaf(v.w, w.w, acc[tt][e]))));
                    }
                }
            }
            __syncthreads();
        }

#pragma unroll
        for (int tt = 0; tt < 2; tt++)
#pragma unroll
            for (int e = 0; e < NE; e++)
                for (int o = 16; o; o >>= 1)
                    acc[tt][e] += __shfl_xor_sync(0xffffffffu, acc[tt][e], o);

        if (lane == 0) {
#pragma unroll
            for (int tt = 0; tt < 2; tt++) {
                float* lg = acc[tt];
                int i1 = 0;
                for (int e = 1; e < NE; e++) if (lg[e] > lg[i1]) i1 = e;
                int i2 = (i1 == 0) ? 1 : 0;
                for (int e = 0; e < NE; e++)
                    if (e != i1 && lg[e] > lg[i2]) i2 = e;
                float e2 = expf(lg[i2] - lg[i1]);
                float inv = 1.f / (1.f + e2);
                float* o = g_gs + (size_t)(t0 + tt) * NE;
#pragma unroll
                for (int e = 0; e < NE; e++) o[e] = 0.f;
                o[i1] = 2.0f * inv;        // SCALING = 2.0 folded
                o[i2] = 2.0f * e2 * inv;
            }
        }
    } else if (bid < PREP_GATE_BLKS + PREP_CONVW_BLKS) {
        // ------- conv: base_w -> g_wh ; lora_A -> g_lah (4-way MLP) -------
        const int n4_base = (DOUT * DIN) / 4;
        const int n4_tot  = n4_base + (JD * DIN) / 4;
        const int stride  = PREP_CONVW_BLKS * 256;
        for (int i0 = (bid - PREP_GATE_BLKS) * 256 + tid; i0 < n4_tot;
             i0 += 4 * stride) {
            float4 v[4];
            bool ok[4];
#pragma unroll
            for (int u = 0; u < 4; u++) {
                int i = i0 + u * stride;
                ok[u] = (i < n4_tot);
                if (ok[u]) v[u] = (i < n4_base) ? bw[i] : la[i - n4_base];
            }
#pragma unroll
            for (int u = 0; u < 4; u++) {
                if (ok[u]) {
                    int i = i0 + u * stride;
                    __half2* o = (i < n4_base)
                        ? reinterpret_cast<__half2*>(g_wh + (size_t)i * 4)
                        : reinterpret_cast<__half2*>(g_lah + (size_t)(i - n4_base) * 4);
                    o[0] = __floats2half2_rn(v[u].x, v[u].y);
                    o[1] = __floats2half2_rn(v[u].z, v[u].w);
                }
            }
        }
    } else {
        // ---------------- conv_bc: lora_B -> Bcat fp16 ----------------
        for (int idx = (bid - PREP_GATE_BLKS - PREP_CONVW_BLKS) * 256 + tid;
             idx < NE * DOUT * RL; idx += 64 * 256) {
            int e = idx >> 16;
            int rem = idx & 0xFFFF;
            int o = rem >> 4;
            int r = rem & 15;
            g_bch[(size_t)o * JD + e * RL + r] = __float2half(lb[idx]);
        }
    }
}

// ---------------------------------------------------------------------------
// Shared GEMM tile machinery constants
// ---------------------------------------------------------------------------
#define BK 64
#define NSTAGE 3
#define T_STAGE (128 * BK * 2)   // 16 KB per operand per stage
#define B_OFF   (NSTAGE * T_STAGE)
#define X_OFF   (2 * NSTAGE * T_STAGE)       // extra buffer for Bcat chunk 0
#define SMEM_LOW  (2 * NSTAGE * T_STAGE)     // 96 KB (k_low)
#define SMEM_G1   (2 * NSTAGE * T_STAGE + T_STAGE)   // 112 KB (gemm1)

// ---------------------------------------------------------------------------
// k_low: split-K GEMM  low_partial[s] = x[., s*512..] @ lora_A[., s*512..]^T
// ---------------------------------------------------------------------------
__global__ void __launch_bounds__(256, 2)
k_low() {
    extern __shared__ __align__(1024) char smem[];
    const uint32_t sbase = smem_u32(smem);

    const int tid = threadIdx.x;
    const int wid = tid >> 5, lane = tid & 31;
    const int warp_m = wid & 1;
    const int warp_n = wid >> 1;
    const int split = blockIdx.x;

    const int ld_row = tid >> 3;
    const int ld_chk = tid & 7;
    const __half* gA = g_xh + ((size_t)blockIdx.y * 128 + ld_row) * DIN +
                       split * (DIN / NSPLIT) + ld_chk * 8;
    const __half* gB = g_lah + (size_t)ld_row * DIN +
                       split * (DIN / NSPLIT) + ld_chk * 8;

    uint32_t stOff[4];
#pragma unroll
    for (int p = 0; p < 4; p++)
        stOff[p] = sw128((uint32_t)(ld_row + 32 * p) * 128 + ld_chk * 16);

    const int aRow = warp_m * 64 + (lane & 15);
    const int aColH = (lane >> 4) * 8;
    const int bRow = warp_n * 32 + (lane & 7) + ((lane >> 4) * 8);
    const int bColH = ((lane >> 3) & 1) * 8;

    float acc[4][4][4];
#pragma unroll
    for (int mi = 0; mi < 4; mi++)
#pragma unroll
        for (int ni = 0; ni < 4; ni++)
#pragma unroll
            for (int c = 0; c < 4; c++) acc[mi][ni][c] = 0.f;

    const int NK = (DIN / NSPLIT) / BK;   // 8

    auto issue = [&](int kstage) {
        const int st = kstage % NSTAGE;
        const __half* ga = gA + kstage * BK;
        const __half* gb = gB + kstage * BK;
        const uint32_t aBuf = sbase + st * T_STAGE;
        const uint32_t bBuf = sbase + B_OFF + st * T_STAGE;
#pragma unroll
        for (int p = 0; p < 4; p++) {
            CP_ASYNC16(aBuf + stOff[p], ga + (size_t)(32 * p) * DIN);
            CP_ASYNC16(bBuf + stOff[p], gb + (size_t)(32 * p) * DIN);
        }
    };

    issue(0); CP_COMMIT();
    issue(1); CP_COMMIT();

    for (int kc = 0; kc < NK; kc++) {
        CP_WAIT1();
        __syncthreads();
        if (kc + 2 < NK) issue(kc + 2);
        CP_COMMIT();

        const uint32_t aT = sbase + (kc % NSTAGE) * T_STAGE;
        const uint32_t bT = sbase + B_OFF + (kc % NSTAGE) * T_STAGE;

#pragma unroll
        for (int ks = 0; ks < BK / 16; ks++) {
            uint32_t af[4][4];
#pragma unroll
            for (int mi = 0; mi < 4; mi++) {
                uint32_t off = (uint32_t)(aRow + mi * 16) * 128 +
                               (uint32_t)(aColH + ks * 16) * 2;
                ldsm_x4(af[mi][0], af[mi][1], af[mi][2], af[mi][3],
                        aT + sw128(off));
            }
            uint32_t bf[2][4];
#pragma unroll
            for (int ni2 = 0; ni2 < 2; ni2++) {
                uint32_t off = (uint32_t)(bRow + ni2 * 16) * 128 +
                               (uint32_t)(bColH + ks * 16) * 2;
                ldsm_x4(bf[ni2][0], bf[ni2][1], bf[ni2][2], bf[ni2][3],
                        bT + sw128(off));
            }
#pragma unroll
            for (int mi = 0; mi < 4; mi++) {
#pragma unroll
                for (int ni = 0; ni < 4; ni++) {
                    uint32_t b0 = bf[ni >> 1][(ni & 1) * 2 + 0];
                    uint32_t b1 = bf[ni >> 1][(ni & 1) * 2 + 1];
                    mma16816(acc[mi][ni][0], acc[mi][ni][1],
                             acc[mi][ni][2], acc[mi][ni][3],
                             af[mi][0], af[mi][1], af[mi][2], af[mi][3],
                             b0, b1);
                }
            }
        }
    }

    float* outp = g_lowp[split];
    const int rowBase = blockIdx.y * 128 + warp_m * 64 + (lane >> 2);
    const int colBase = warp_n * 32 + (lane & 3) * 2;
#pragma unroll
    for (int mi = 0; mi < 4; mi++) {
#pragma unroll
        for (int ni = 0; ni < 4; ni++) {
            int r0 = rowBase + mi * 16;
            int c0 = colBase + ni * 8;
            float2* o = reinterpret_cast<float2*>(outp + (size_t)r0 * JD + c0);
            o[0] = make_float2(acc[mi][ni][0], acc[mi][ni][1]);
            o = reinterpret_cast<float2*>(outp + (size_t)(r0 + 8) * JD + c0);
            o[0] = make_float2(acc[mi][ni][2], acc[mi][ni][3]);
        }
    }
}

// ---------------------------------------------------------------------------
// k_z: z = gs * sum_s lowp[s] -> fp16   (float4-vectorized)
// ---------------------------------------------------------------------------
__global__ void __launch_bounds__(256) k_z() {
    int i = blockIdx.x * blockDim.x + threadIdx.x;   // float4 index
    if (i < TOK * JD / 4) {
        int t = i >> 5;
        int j = (i & 31) * 4;
        float4 s = make_float4(0.f, 0.f, 0.f, 0.f);
#pragma unroll
        for (int sp = 0; sp < NSPLIT; sp++) {
            float4 p = reinterpret_cast<const float4*>(g_lowp[sp])[i];
            s.x += p.x; s.y += p.y; s.z += p.z; s.w += p.w;
        }
        float g = g_gs[(size_t)t * NE + (j >> 4)];
        __half2* o = reinterpret_cast<__half2*>(g_zh) + 2 * i;
        o[0] = __floats2half2_rn(g * s.x, g * s.y);
        o[1] = __floats2half2_rn(g * s.z, g * s.w);
    }
}

// ---------------------------------------------------------------------------
// k_gemm1: out = x @ base_w^T + bias + z @ Bcat^T
//   R15 mainloop + Bcat chunk-0 prologue prefetch.
//   Epilogue: bias hoisted out of mi loop (8 LDG not 32), float2 stores.
// ---------------------------------------------------------------------------
__global__ void __launch_bounds__(256, 2)
k_gemm1(const float* __restrict__ bias, float* __restrict__ out) {
    extern __shared__ __align__(1024) char smem[];
    const uint32_t sbase = smem_u32(smem);

    const int tid = threadIdx.x;
    const int wid = tid >> 5, lane = tid & 31;
    const int warp_m = wid & 1;
    const int warp_n = wid >> 1;

    const int ld_row = tid >> 3;
    const int ld_chk = tid & 7;
    const __half* gA = g_xh + ((size_t)blockIdx.y * 128 + ld_row) * DIN + ld_chk * 8;
    const __half* gB = g_wh + ((size_t)blockIdx.x * 128 + ld_row) * DIN + ld_chk * 8;
    const __half* gC = g_bch + ((size_t)blockIdx.x * 128 + ld_row) * JD + ld_chk * 8;

    uint32_t stOff[4];
#pragma unroll
    for (int p = 0; p < 4; p++)
        stOff[p] = sw128((uint32_t)(ld_row + 32 * p) * 128 + ld_chk * 16);

    const int aRow = warp_m * 64 + (lane & 15);
    const int aColH = (lane >> 4) * 8;
    const int bRow = warp_n * 32 + (lane & 7) + ((lane >> 4) * 8);
    const int bColH = ((lane >> 3) & 1) * 8;

    float acc[4][4][4];
#pragma unroll
    for (int mi = 0; mi < 4; mi++)
#pragma unroll
        for (int ni = 0; ni < 4; ni++)
#pragma unroll
            for (int c = 0; c < 4; c++) acc[mi][ni][c] = 0.f;

    const int NK = DIN / BK;

    auto issue = [&](int kstage) {
        const int st = kstage % NSTAGE;
        const __half* ga = gA + kstage * BK;
        const __half* gb = gB + kstage * BK;
        const uint32_t aBuf = sbase + st * T_STAGE;
        const uint32_t bBuf = sbase + B_OFF + st * T_STAGE;
#pragma unroll
        for (int p = 0; p < 4; p++) {
            CP_ASYNC16(aBuf + stOff[p], ga + (size_t)(32 * p) * DIN);
            CP_ASYNC16(bBuf + stOff[p], gb + (size_t)(32 * p) * DIN);
        }
    };

    // prologue: stage 0 + Bcat chunk 0 (into extra buffer) in one group
    issue(0);
#pragma unroll
    for (int p = 0; p < 4; p++)
        CP_ASYNC16(sbase + X_OFF + stOff[p], gC + (size_t)(32 * p) * JD);
    CP_COMMIT();
    issue(1); CP_COMMIT();

    for (int kc = 0; kc < NK; kc++) {
        CP_WAIT1();
        __syncthreads();
        if (kc + 2 < NK) issue(kc + 2);
        CP_COMMIT();

        const uint32_t aT = sbase + (kc % NSTAGE) * T_STAGE;
        const uint32_t bT = sbase + B_OFF + (kc % NSTAGE) * T_STAGE;

#pragma unroll
        for (int ks = 0; ks < BK / 16; ks++) {
            uint32_t af[4][4];
#pragma unroll
            for (int mi = 0; mi < 4; mi++) {
                uint32_t off = (uint32_t)(aRow + mi * 16) * 128 +
                               (uint32_t)(aColH + ks * 16) * 2;
                ldsm_x4(af[mi][0], af[mi][1], af[mi][2], af[mi][3],
                        aT + sw128(off));
            }
            uint32_t bf[2][4];
#pragma unroll
            for (int ni2 = 0; ni2 < 2; ni2++) {
                uint32_t off = (uint32_t)(bRow + ni2 * 16) * 128 +
                               (uint32_t)(bColH + ks * 16) * 2;
                ldsm_x4(bf[ni2][0], bf[ni2][1], bf[ni2][2], bf[ni2][3],
                        bT + sw128(off));
            }
#pragma unroll
            for (int mi = 0; mi < 4; mi++) {
#pragma unroll
                for (int ni = 0; ni < 4; ni++) {
                    uint32_t b0 = bf[ni >> 1][(ni & 1) * 2 + 0];
                    uint32_t b1 = bf[ni >> 1][(ni & 1) * 2 + 1];
                    mma16816(acc[mi][ni][0], acc[mi][ni][1],
                             acc[mi][ni][2], acc[mi][ni][3],
                             af[mi][0], af[mi][1], af[mi][2], af[mi][3],
                             b0, b1);
                }
            }
        }
    }

    // ---------------- LoRA tail: acc += z @ Bcat^T (K = JD = 128) ----------
    __syncthreads();   // all warps done reading stage buffers
    {
        const __half* gZ = g_zh + ((size_t)blockIdx.y * 128 + ld_row) * JD + ld_chk * 8;
#pragma unroll
        for (int kc = 0; kc < 2; kc++) {
#pragma unroll
            for (int p = 0; p < 4; p++)
                CP_ASYNC16(sbase + kc * T_STAGE + stOff[p],
                           gZ + kc * 64 + (size_t)(32 * p) * JD);
        }
#pragma unroll
        for (int p = 0; p < 4; p++)
            CP_ASYNC16(sbase + B_OFF + stOff[p],
                       gC + 64 + (size_t)(32 * p) * JD);
        CP_COMMIT();
        CP_WAIT0();
        __syncthreads();

#pragma unroll
        for (int kc = 0; kc < 2; kc++) {
            const uint32_t aT = sbase + kc * T_STAGE;
            const uint32_t bT = (kc == 0) ? (sbase + X_OFF) : (sbase + B_OFF);
#pragma unroll
            for (int ks = 0; ks < 4; ks++) {
                uint32_t af[4][4];
#pragma unroll
                for (int mi = 0; mi < 4; mi++) {
                    uint32_t off = (uint32_t)(aRow + mi * 16) * 128 +
                                   (uint32_t)(aColH + ks * 16) * 2;
                    ldsm_x4(af[mi][0], af[mi][1], af[mi][2], af[mi][3],
                            aT + sw128(off));
                }
                uint32_t bf[2][4];
#pragma unroll
                for (int ni2 = 0; ni2 < 2; ni2++) {
                    uint32_t off = (uint32_t)(bRow + ni2 * 16) * 128 +
                                   (uint32_t)(bColH + ks * 16) * 2;
                    ldsm_x4(bf[ni2][0], bf[ni2][1], bf[ni2][2], bf[ni2][3],
                            bT + sw128(off));
                }
#pragma unroll
                for (int mi = 0; mi < 4; mi++) {
#pragma unroll
                    for (int ni = 0; ni < 4; ni++) {
                        uint32_t b0 = bf[ni >> 1][(ni & 1) * 2 + 0];
                        uint32_t b1 = bf[ni >> 1][(ni & 1) * 2 + 1];
                        mma16816(acc[mi][ni][0], acc[mi][ni][1],
                                 acc[mi][ni][2], acc[mi][ni][3],
                                 af[mi][0], af[mi][1], af[mi][2], af[mi][3],
                                 b0, b1);
                    }
                }
            }
        }
    }

    // ------- epilogue: out = acc + bias (hoisted bias, float2 stores) ------
    const int rowBase = blockIdx.y * 128 + warp_m * 64 + (lane >> 2);
    const int colBase = blockIdx.x * 128 + warp_n * 32 + (lane & 3) * 2;

    float bb[4][2];
#pragma unroll
    for (int ni = 0; ni < 4; ni++) {
        bb[ni][0] = __ldg(bias + colBase + ni * 8);
        bb[ni][1] = __ldg(bias + colBase + ni * 8 + 1);
    }

#pragma unroll
    for (int mi = 0; mi < 4; mi++) {
#pragma unroll
        for (int ni = 0; ni < 4; ni++) {
            int r0 = rowBase + mi * 16;
            int c0 = colBase + ni * 8;
            float2* o = reinterpret_cast<float2*>(out + (size_t)r0 * DOUT + c0);
            o[0] = make_float2(acc[mi][ni][0] + bb[ni][0],
                               acc[mi][ni][1] + bb[ni][1]);
            o = reinterpret_cast<float2*>(out + (size_t)(r0 + 8) * DOUT + c0);
            o[0] = make_float2(acc[mi][ni][2] + bb[ni][0],
                               acc[mi][ni][3] + bb[ni][1]);
        }
    }
}

// ---------------------------------------------------------------------------
// Launcher (single stream, best-known ordering)
// ---------------------------------------------------------------------------
extern "C" void kernel_launch(void* const* d_in, const int* in_sizes, int n_in,
                              void* d_out, int out_size) {
    const float* x      = (const float*)d_in[0];
    const float* gate_w = (const float*)d_in[1];
    const float* base_w = (const float*)d_in[2];
    const float* base_b = (const float*)d_in[3];
    const float* lora_A = (const float*)d_in[4];
    const float* lora_B = (const float*)d_in[5];
    float* out = (float*)d_out;

    cudaFuncSetAttribute(k_low,
                         cudaFuncAttributeMaxDynamicSharedMemorySize, SMEM_LOW);
    cudaFuncSetAttribute(k_gemm1,
                         cudaFuncAttributeMaxDynamicSharedMemorySize, SMEM_G1);

    // 1. prep: gate (+x conversion) | base_w/lora_A conversion | Bcat pack
    k_prep<<<PREP_GRID, 256>>>(x, gate_w, (const float4*)base_w,
                               (const float4*)lora_A, lora_B);

    // 2. low-rank activations, split-K partials
    k_low<<<dim3(NSPLIT, TOK / 128), 256, SMEM_LOW>>>();

    // 3. reduce partials, apply routing weights, emit fp16 z
    k_z<<<(TOK * JD / 4 + 255) / 256, 256>>>();

    // 4. fused: out = x@W^T + bias + z@Bcat^T
    k_gemm1<<<dim3(DOUT / 128, TOK / 128), 256, SMEM_G1>>>(base_b, out);
}